// round 1
// baseline (speedup 1.0000x reference)
#include <cuda_runtime.h>
#include <math.h>

// Problem shape (fixed by the dataset)
// x:      [8, 4096, 512]  float32
// w_qkv:  [512, 1536]
// b_qkv:  [1536]
// w_proj: [512, 512]
// b_proj: [512]
// out:    [8, 4096, 512]  float32

constexpr int B_   = 8;
constexpr int N_   = 4096;
constexpr int C_   = 512;
constexpr int H_   = 8;
constexpr int D_   = 64;      // head dim
constexpr int MTOK = B_ * N_; // 32768 tokens
constexpr int C3   = 3 * C_;  // 1536

// -------- scratch (static device globals; no allocation allowed) ----------
__device__ float g_qkv[(size_t)MTOK * C3];   // [tok, 1536]  q|k|v, head-major within each
__device__ float g_rq[MTOK * H_];            // per (tok, head) q scale = d^-.5 * rsqrt(sumsq)
__device__ float g_rk[MTOK * H_];            // per (tok, head) k scale = rsqrt(sumsq)
__device__ float g_attn[B_ * H_ * D_ * D_];  // [bh, d, e]
__device__ float g_mid[(size_t)MTOK * C_];   // v @ attn, laid out [tok, h*64+e]

// ======================= SGEMM (row-major, + bias over N) =================
// C[M,N] = A[M,K] @ B[K,N] + bias[N].  BM=BN=128, BK=8, 256 threads, 8x8/thread.
// Requires M%128==0, N%128==0, K%8==0 (true for all our shapes).
__global__ __launch_bounds__(256) void sgemm_bias_kernel(
    const float* __restrict__ A, const float* __restrict__ Bm,
    const float* __restrict__ bias, float* __restrict__ Cm,
    int M, int N, int K)
{
    constexpr int BM = 128, BN = 128, BK = 8, TM = 8, TN = 8;
    __shared__ __align__(16) float As[BK][BM];
    __shared__ __align__(16) float Bs[BK][BN];

    const int tid = threadIdx.x;
    const int tx  = tid & 15;      // 0..15  -> N direction
    const int ty  = tid >> 4;      // 0..15  -> M direction

    const size_t block_row = blockIdx.y;  // tile in M
    const size_t block_col = blockIdx.x;  // tile in N

    const float* A0 = A + block_row * BM * (size_t)K;
    const float* B0 = Bm + block_col * BN;

    // load mapping
    const int a_row = tid >> 1;          // 0..127
    const int a_col = (tid & 1) * 4;     // 0 or 4
    const int b_row = tid >> 5;          // 0..7
    const int b_col = (tid & 31) * 4;    // 0..124

    float acc[TM][TN];
    #pragma unroll
    for (int i = 0; i < TM; i++)
        #pragma unroll
        for (int j = 0; j < TN; j++) acc[i][j] = 0.f;

    for (int k0 = 0; k0 < K; k0 += BK) {
        float4 av = *(const float4*)(A0 + (size_t)a_row * K + k0 + a_col);
        As[a_col + 0][a_row] = av.x;
        As[a_col + 1][a_row] = av.y;
        As[a_col + 2][a_row] = av.z;
        As[a_col + 3][a_row] = av.w;
        *(float4*)&Bs[b_row][b_col] =
            *(const float4*)(B0 + (size_t)(k0 + b_row) * N + b_col);
        __syncthreads();

        #pragma unroll
        for (int kk = 0; kk < BK; kk++) {
            float4 a0 = *(const float4*)&As[kk][ty * TM];
            float4 a1 = *(const float4*)&As[kk][ty * TM + 4];
            float4 b0 = *(const float4*)&Bs[kk][tx * TN];
            float4 b1 = *(const float4*)&Bs[kk][tx * TN + 4];
            float ra[TM] = {a0.x, a0.y, a0.z, a0.w, a1.x, a1.y, a1.z, a1.w};
            float rb[TN] = {b0.x, b0.y, b0.z, b0.w, b1.x, b1.y, b1.z, b1.w};
            #pragma unroll
            for (int i = 0; i < TM; i++)
                #pragma unroll
                for (int j = 0; j < TN; j++)
                    acc[i][j] = fmaf(ra[i], rb[j], acc[i][j]);
        }
        __syncthreads();
    }

    // epilogue: + bias, store
    #pragma unroll
    for (int i = 0; i < TM; i++) {
        size_t r = block_row * BM + ty * TM + i;
        #pragma unroll
        for (int j = 0; j < TN; j += 4) {
            size_t c = block_col * BN + tx * TN + j;
            float4 o;
            o.x = acc[i][j + 0] + bias[c + 0];
            o.y = acc[i][j + 1] + bias[c + 1];
            o.z = acc[i][j + 2] + bias[c + 2];
            o.w = acc[i][j + 3] + bias[c + 3];
            *(float4*)(Cm + r * N + c) = o;
        }
    }
}

// ==================== per-(token, head) L2-norm factors ====================
// One warp handles one (token, head): reduces 64 q values and 64 k values.
__global__ __launch_bounds__(256) void norms_kernel()
{
    int gwarp = (blockIdx.x * blockDim.x + threadIdx.x) >> 5;
    int lane  = threadIdx.x & 31;
    if (gwarp >= MTOK * H_) return;
    int t  = gwarp >> 3;       // token
    int hh = gwarp & 7;        // head

    const float* qrow = g_qkv + (size_t)t * C3 + hh * D_;
    const float* krow = qrow + C_;  // k block offset = 512

    float q0 = qrow[lane], q1 = qrow[lane + 32];
    float k0 = krow[lane], k1 = krow[lane + 32];
    float sq = q0 * q0 + q1 * q1;
    float sk = k0 * k0 + k1 * k1;
    #pragma unroll
    for (int o = 16; o; o >>= 1) {
        sq += __shfl_xor_sync(0xFFFFFFFFu, sq, o);
        sk += __shfl_xor_sync(0xFFFFFFFFu, sk, o);
    }
    if (lane == 0) {
        g_rq[t * H_ + hh] = 0.125f * rsqrtf(fmaxf(sq, 1e-12f)); // * d^-0.5
        g_rk[t * H_ + hh] = rsqrtf(fmaxf(sk, 1e-12f));
    }
}

// ============================ zero attn accumulator ========================
__global__ void zero_attn_kernel()
{
    int i = blockIdx.x * blockDim.x + threadIdx.x;
    if (i < B_ * H_ * D_ * D_) g_attn[i] = 0.f;
}

// =================== attn[bh,d,e] = sum_n q~[n,d] * k~[n,e] ================
// grid.x = 16 token chunks (256 tokens each), grid.y = 64 (b*8+h).
// Each block accumulates its chunk's 64x64 outer-product sum, atomicAdd out.
__global__ __launch_bounds__(256) void attn_qk_kernel()
{
    constexpr int TOKS = 32;   // tokens per sub-tile
    __shared__ __align__(16) float qs[TOKS][68];  // padded rows
    __shared__ __align__(16) float ks[TOKS][68];

    const int tid = threadIdx.x;
    const int tx  = tid & 15;    // e group (4 cols)
    const int ty  = tid >> 4;    // d group (4 rows)
    const int bh  = blockIdx.y;  // 0..63
    const int b   = bh >> 3;
    const int hh  = bh & 7;
    const int tok_base = blockIdx.x * 256;   // within this batch's 4096 tokens

    float acc[4][4];
    #pragma unroll
    for (int i = 0; i < 4; i++)
        #pragma unroll
        for (int j = 0; j < 4; j++) acc[i][j] = 0.f;

    for (int sub = 0; sub < 256; sub += TOKS) {
        // load 32 tokens x 64 dims of q and k (scaled), float4 per thread x2
        #pragma unroll
        for (int it = 0; it < 2; it++) {
            int fid = tid + it * 256;         // 0..511 float4 slots
            int tl  = fid >> 4;               // token_local 0..31
            int d4  = fid & 15;               // float4 index in d
            int t   = b * N_ + tok_base + sub + tl;           // global token row
            const float* base = g_qkv + (size_t)t * C3 + hh * D_ + d4 * 4;
            float rq = g_rq[t * H_ + hh];
            float rk = g_rk[t * H_ + hh];
            float4 qv = *(const float4*)base;
            float4 kv = *(const float4*)(base + C_);
            qv.x *= rq; qv.y *= rq; qv.z *= rq; qv.w *= rq;
            kv.x *= rk; kv.y *= rk; kv.z *= rk; kv.w *= rk;
            *(float4*)&qs[tl][d4 * 4] = qv;
            *(float4*)&ks[tl][d4 * 4] = kv;
        }
        __syncthreads();

        #pragma unroll 4
        for (int tok = 0; tok < TOKS; tok++) {
            float4 qd = *(const float4*)&qs[tok][ty * 4];
            float4 ke = *(const float4*)&ks[tok][tx * 4];
            float rd[4] = {qd.x, qd.y, qd.z, qd.w};
            float re[4] = {ke.x, ke.y, ke.z, ke.w};
            #pragma unroll
            for (int i = 0; i < 4; i++)
                #pragma unroll
                for (int j = 0; j < 4; j++)
                    acc[i][j] = fmaf(rd[i], re[j], acc[i][j]);
        }
        __syncthreads();
    }

    float* out = g_attn + (size_t)bh * D_ * D_;
    #pragma unroll
    for (int i = 0; i < 4; i++)
        #pragma unroll
        for (int j = 0; j < 4; j++)
            atomicAdd(&out[(ty * 4 + i) * D_ + tx * 4 + j], acc[i][j]);
}

// ===================== softmax over last axis (64 wide) ====================
__global__ __launch_bounds__(64) void softmax_kernel()
{
    __shared__ float red[64];
    float* p = g_attn + (size_t)blockIdx.x * 64;
    int t = threadIdx.x;
    float v = p[t];
    red[t] = v; __syncthreads();
    #pragma unroll
    for (int s = 32; s; s >>= 1) { if (t < s) red[t] = fmaxf(red[t], red[t + s]); __syncthreads(); }
    float m = red[0]; __syncthreads();
    float e = __expf(v - m);
    red[t] = e; __syncthreads();
    #pragma unroll
    for (int s = 32; s; s >>= 1) { if (t < s) red[t] += red[t + s]; __syncthreads(); }
    p[t] = e / red[0];
}

// =============== mid[tok, h*64+e] = sum_d v[tok,d] * attn[bh,d,e] ==========
// grid.x = 64 token chunks (64 tokens), grid.y = 64 (b*8+h).
__global__ __launch_bounds__(256) void v_attn_kernel()
{
    __shared__ __align__(16) float at[D_][D_];   // 16KB
    __shared__ __align__(16) float vs[D_][D_];   // 16KB (tok x d)

    const int tid = threadIdx.x;
    const int bh  = blockIdx.y;
    const int b   = bh >> 3;
    const int hh  = bh & 7;
    const int tok0 = blockIdx.x * 64;  // within batch

    // load attn tile: 1024 float4s
    const float* ap = g_attn + (size_t)bh * D_ * D_;
    #pragma unroll
    for (int it = 0; it < 4; it++) {
        int fid = tid + it * 256;
        ((float4*)at)[fid] = ((const float4*)ap)[fid];
    }
    // load v tile: 64 tokens x 64 dims
    #pragma unroll
    for (int it = 0; it < 4; it++) {
        int fid = tid + it * 256;
        int tl = fid >> 4, d4 = fid & 15;
        int t  = b * N_ + tok0 + tl;
        *(float4*)&vs[tl][d4 * 4] =
            *(const float4*)(g_qkv + (size_t)t * C3 + 2 * C_ + hh * D_ + d4 * 4);
    }
    __syncthreads();

    const int rg = tid >> 4;   // token group: 4 tokens
    const int cg = tid & 15;   // e group: 4 cols
    float acc[4][4];
    #pragma unroll
    for (int i = 0; i < 4; i++)
        #pragma unroll
        for (int j = 0; j < 4; j++) acc[i][j] = 0.f;

    #pragma unroll 8
    for (int d = 0; d < D_; d++) {
        float4 a4 = *(const float4*)&at[d][cg * 4];
        float ae[4] = {a4.x, a4.y, a4.z, a4.w};
        #pragma unroll
        for (int i = 0; i < 4; i++) {
            float va = vs[rg * 4 + i][d];
            #pragma unroll
            for (int j = 0; j < 4; j++)
                acc[i][j] = fmaf(va, ae[j], acc[i][j]);
        }
    }

    #pragma unroll
    for (int i = 0; i < 4; i++) {
        int t = b * N_ + tok0 + rg * 4 + i;
        float4 o = {acc[i][0], acc[i][1], acc[i][2], acc[i][3]};
        *(float4*)(g_mid + (size_t)t * C_ + hh * D_ + cg * 4) = o;
    }
}

// ================================ launch ===================================
extern "C" void kernel_launch(void* const* d_in, const int* in_sizes, int n_in,
                              void* d_out, int out_size)
{
    const float* x      = (const float*)d_in[0];
    const float* w_qkv  = (const float*)d_in[1];
    const float* b_qkv  = (const float*)d_in[2];
    const float* w_proj = (const float*)d_in[3];
    const float* b_proj = (const float*)d_in[4];
    float* out = (float*)d_out;

    float* qkv_ptr; cudaGetSymbolAddress((void**)&qkv_ptr, g_qkv);
    float* mid_ptr; cudaGetSymbolAddress((void**)&mid_ptr, g_mid);

    // 1) qkv = x @ w_qkv + b_qkv     [32768,512]x[512,1536]
    {
        dim3 grid(C3 / 128, MTOK / 128);
        sgemm_bias_kernel<<<grid, 256>>>(x, w_qkv, b_qkv, qkv_ptr, MTOK, C3, C_);
    }
    // 2) per-(token, head) rsqrt norm factors for q and k
    norms_kernel<<<(MTOK * H_) / 8, 256>>>();
    // 3) attn = sum_n q~ k~  (chunked, atomic accumulate)
    zero_attn_kernel<<<(B_ * H_ * D_ * D_ + 255) / 256, 256>>>();
    {
        dim3 grid(N_ / 256, B_ * H_);
        attn_qk_kernel<<<grid, 256>>>();
    }
    // 4) softmax over e
    softmax_kernel<<<B_ * H_ * D_, 64>>>();
    // 5) mid = v @ attn
    {
        dim3 grid(N_ / 64, B_ * H_);
        v_attn_kernel<<<grid, 256>>>();
    }
    // 6) out = mid @ w_proj + b_proj   [32768,512]x[512,512]
    {
        dim3 grid(C_ / 128, MTOK / 128);
        sgemm_bias_kernel<<<grid, 256>>>(mid_ptr, w_proj, b_proj, out, MTOK, C_, C_);
    }
}

// round 3
// speedup vs baseline: 1.9863x; 1.9863x over previous
#include <cuda_runtime.h>
#include <cuda_bf16.h>
#include <math.h>
#include <stdint.h>

// Shapes (fixed): x[8,4096,512] f32, w_qkv[512,1536], b_qkv[1536],
// w_proj[512,512], b_proj[512], out[8,4096,512] f32.
constexpr int B_   = 8;
constexpr int N_   = 4096;
constexpr int C_   = 512;
constexpr int H_   = 8;
constexpr int D_   = 64;
constexpr int MTOK = B_ * N_;   // 32768
constexpr int C3   = 3 * C_;    // 1536
constexpr int KS   = 1536;      // split-K': A=[hi|lo|hi], B=[hi|hi|lo]

// ------------------------- device scratch (static) -------------------------
__device__ __nv_bfloat16 g_xs[(size_t)MTOK * KS];   // split x        (A of qkv gemm)
__device__ __nv_bfloat16 g_ms[(size_t)MTOK * KS];   // split mid      (A of proj gemm)
__device__ __nv_bfloat16 g_wq[(size_t)C3 * KS];     // split w_qkv^T  [n][k']
__device__ __nv_bfloat16 g_wp[(size_t)C_ * KS];     // split w_proj^T [n][k']
__device__ float g_qkv[(size_t)MTOK * C3];          // qkv fp32 [tok][1536]
__device__ float g_rq[MTOK * H_];
__device__ float g_rk[MTOK * H_];
__device__ float g_attn[B_ * H_ * D_ * D_];

// ----------------------------- helpers ------------------------------------
__device__ __forceinline__ uint32_t smem_u32(const void* p) {
    uint32_t a;
    asm("{ .reg .u64 t; cvta.to.shared.u64 t, %1; cvt.u32.u64 %0, t; }"
        : "=r"(a) : "l"(p));
    return a;
}
__device__ __forceinline__ uint32_t packbf(float a, float b) {
    __nv_bfloat162 p = __floats2bfloat162_rn(a, b);
    return *(uint32_t*)&p;
}
__device__ __forceinline__ float bfr(float v) {  // value after bf16 round
    return __bfloat162float(__float2bfloat16(v));
}

#define CP_ASYNC16(dst_u32, src_ptr) \
    asm volatile("cp.async.cg.shared.global [%0], [%1], 16;" \
        :: "r"(dst_u32), "l"(src_ptr))
#define CP_COMMIT()  asm volatile("cp.async.commit_group;")
#define CP_WAIT0()   asm volatile("cp.async.wait_group 0;" ::: "memory")

__device__ __forceinline__ void ldmatrix_x4(uint32_t* r, uint32_t addr) {
    asm volatile("ldmatrix.sync.aligned.m8n8.x4.shared.b16 {%0,%1,%2,%3}, [%4];"
        : "=r"(r[0]), "=r"(r[1]), "=r"(r[2]), "=r"(r[3]) : "r"(addr));
}
__device__ __forceinline__ void mma_bf16(float* c, const uint32_t* a,
                                         uint32_t b0, uint32_t b1) {
    asm volatile(
        "mma.sync.aligned.m16n8k16.row.col.f32.bf16.bf16.f32 "
        "{%0,%1,%2,%3}, {%4,%5,%6,%7}, {%8,%9}, {%0,%1,%2,%3};"
        : "+f"(c[0]), "+f"(c[1]), "+f"(c[2]), "+f"(c[3])
        : "r"(a[0]), "r"(a[1]), "r"(a[2]), "r"(a[3]), "r"(b0), "r"(b1));
}

// =========================== split prep kernels ============================
// g_xs[t][0:512)=hi(x), [512:1024)=lo(x), [1024:1536)=hi(x)
__global__ __launch_bounds__(256) void split_x_kernel(const float* __restrict__ x)
{
    size_t fid = (size_t)blockIdx.x * 256 + threadIdx.x;  // MTOK*128 float4s
    size_t t = fid >> 7;
    int c4 = (int)(fid & 127);
    float4 v = ((const float4*)x)[fid];
    float hx = bfr(v.x), hy = bfr(v.y), hz = bfr(v.z), hw = bfr(v.w);
    uint2 hi, lo;
    hi.x = packbf(v.x, v.y); hi.y = packbf(v.z, v.w);
    lo.x = packbf(v.x - hx, v.y - hy); lo.y = packbf(v.z - hz, v.w - hw);
    __nv_bfloat16* base = g_xs + t * KS + c4 * 4;
    *(uint2*)(base)        = hi;
    *(uint2*)(base + 512)  = lo;
    *(uint2*)(base + 1024) = hi;
}

// W[512][Ntot] -> out[n][k'] transposed split: [0:512)=hi, [512:1024)=hi, [1024:1536)=lo
__global__ __launch_bounds__(256) void split_w_kernel(const float* __restrict__ W,
                                                      __nv_bfloat16* __restrict__ out,
                                                      int Ntot)
{
    __shared__ float tile[32][33];
    int n0 = blockIdx.x * 32, k0 = blockIdx.y * 32;
    int tx = threadIdx.x & 31, ty = threadIdx.x >> 5;  // ty 0..7
    #pragma unroll
    for (int i = 0; i < 32; i += 8)
        tile[ty + i][tx] = W[(size_t)(k0 + ty + i) * Ntot + n0 + tx];
    __syncthreads();
    #pragma unroll
    for (int i = 0; i < 32; i += 8) {
        float v = tile[tx][ty + i];              // = W[k0+tx][n0+ty+i]
        __nv_bfloat16 h = __float2bfloat16(v);
        __nv_bfloat16 l = __float2bfloat16(v - __bfloat162float(h));
        __nv_bfloat16* o = out + (size_t)(n0 + ty + i) * KS + k0 + tx;
        o[0] = h; o[512] = h; o[1024] = l;
    }
}

// ================== mma.sync bf16 GEMM, 128x128 CTA tile ===================
// C[M,Ntot] = Asplit[M,1536] @ Bsplit[Ntot,1536]^T + bias, fp32 out.
// 8 warps in 2x4 grid; warp tile 64x32; BK=32; double-buffered cp.async.
constexpr int NKC = KS / 32;       // 48 k-chunks
constexpr int APITCH = 40;         // bf16 elems per smem row (80B: conflict-free)

__global__ __launch_bounds__(256, 2) void gemm_mma_kernel(
    const __nv_bfloat16* __restrict__ A, const __nv_bfloat16* __restrict__ Bm,
    const float* __restrict__ bias, float* __restrict__ C, int Ntot)
{
    __shared__ __align__(16) __nv_bfloat16 As[2][128][APITCH];
    __shared__ __align__(16) __nv_bfloat16 Bs[2][128][APITCH];

    const int tid  = threadIdx.x;
    const int lane = tid & 31;
    const int wid  = tid >> 5;
    const int wr   = wid & 1;     // warp row (0-1): 64 rows each
    const int wc   = wid >> 1;    // warp col (0-3): 32 cols each
    const size_t rowA0 = (size_t)blockIdx.y * 128;
    const size_t rowB0 = (size_t)blockIdx.x * 128;

    // gmem->smem copy mapping: 2 x 16B per thread per operand per stage
    const int cp_row = tid >> 1;               // 0..127 (for idx = tid + i*256: row = idx/4... )
    // idx = tid + i*256, row = idx >> 2, c16 = idx & 3
    const __nv_bfloat16* Abase = A + rowA0 * KS;
    const __nv_bfloat16* Bbase = Bm + rowB0 * KS;
    (void)cp_row;

    uint32_t as_base = smem_u32(&As[0][0][0]);
    uint32_t bs_base = smem_u32(&Bs[0][0][0]);
    constexpr uint32_t BUF_BYTES = 128 * APITCH * 2;  // 10240

    auto stage_copy = [&](int kc, int buf) {
        #pragma unroll
        for (int i = 0; i < 2; i++) {
            int idx = tid + i * 256;           // 0..511
            int r = idx >> 2, c16 = idx & 3;   // c16*8 bf16 offset
            const __nv_bfloat16* g = Abase + (size_t)r * KS + kc * 32 + c16 * 8;
            uint32_t d = as_base + buf * BUF_BYTES + (uint32_t)(r * 80 + c16 * 16);
            CP_ASYNC16(d, g);
        }
        #pragma unroll
        for (int i = 0; i < 2; i++) {
            int idx = tid + i * 256;
            int r = idx >> 2, c16 = idx & 3;
            const __nv_bfloat16* g = Bbase + (size_t)r * KS + kc * 32 + c16 * 8;
            uint32_t d = bs_base + buf * BUF_BYTES + (uint32_t)(r * 80 + c16 * 16);
            CP_ASYNC16(d, g);
        }
        CP_COMMIT();
    };

    float acc[4][4][4];
    #pragma unroll
    for (int i = 0; i < 4; i++)
        #pragma unroll
        for (int j = 0; j < 4; j++)
            #pragma unroll
            for (int k = 0; k < 4; k++) acc[i][j][k] = 0.f;

    // ldmatrix source addresses (byte offsets within a buffer)
    const int a_row = wr * 64 + (lane & 7) + ((lane >> 3) & 1) * 8;
    const int a_k8  = ((lane >> 4) & 1) * 8;
    const int b_row = wc * 32 + (lane & 7) + ((lane >> 4) & 1) * 8;
    const int b_k8  = ((lane >> 3) & 1) * 8;

    stage_copy(0, 0);
    CP_WAIT0();
    __syncthreads();

    #pragma unroll 1
    for (int kc = 0; kc < NKC; kc++) {
        const int buf = kc & 1;
        if (kc + 1 < NKC) stage_copy(kc + 1, buf ^ 1);

        const uint32_t ab = as_base + buf * BUF_BYTES;
        const uint32_t bb = bs_base + buf * BUF_BYTES;
        #pragma unroll
        for (int ks = 0; ks < 2; ks++) {
            uint32_t afr[4][4];
            #pragma unroll
            for (int mi = 0; mi < 4; mi++)
                ldmatrix_x4(afr[mi],
                    ab + (uint32_t)((a_row + mi * 16) * 80 + (ks * 16 + a_k8) * 2));
            uint32_t bfrg[2][4];
            #pragma unroll
            for (int nj2 = 0; nj2 < 2; nj2++)
                ldmatrix_x4(bfrg[nj2],
                    bb + (uint32_t)((b_row + nj2 * 16) * 80 + (ks * 16 + b_k8) * 2));
            #pragma unroll
            for (int mi = 0; mi < 4; mi++) {
                #pragma unroll
                for (int nj = 0; nj < 4; nj++) {
                    uint32_t b0 = bfrg[nj >> 1][(nj & 1) * 2];
                    uint32_t b1 = bfrg[nj >> 1][(nj & 1) * 2 + 1];
                    mma_bf16(acc[mi][nj], afr[mi], b0, b1);
                }
            }
        }
        if (kc + 1 < NKC) CP_WAIT0();
        __syncthreads();
    }

    // epilogue: direct stores + bias
    #pragma unroll
    for (int mi = 0; mi < 4; mi++) {
        size_t r0 = rowA0 + wr * 64 + mi * 16 + (lane >> 2);
        size_t r1 = r0 + 8;
        #pragma unroll
        for (int nj = 0; nj < 4; nj++) {
            size_t col = rowB0 + wc * 32 + nj * 8 + (lane & 3) * 2;
            float b0 = __ldg(&bias[col]), b1 = __ldg(&bias[col + 1]);
            float2 v0 = {acc[mi][nj][0] + b0, acc[mi][nj][1] + b1};
            float2 v1 = {acc[mi][nj][2] + b0, acc[mi][nj][3] + b1};
            *(float2*)(C + r0 * (size_t)Ntot + col) = v0;
            *(float2*)(C + r1 * (size_t)Ntot + col) = v1;
        }
    }
}

// ==================== per-(token, head) L2-norm factors ====================
__global__ __launch_bounds__(256) void norms_kernel()
{
    int gwarp = (blockIdx.x * blockDim.x + threadIdx.x) >> 5;
    int lane  = threadIdx.x & 31;
    if (gwarp >= MTOK * H_) return;
    int t = gwarp >> 3, hh = gwarp & 7;
    const float* qrow = g_qkv + (size_t)t * C3 + hh * D_;
    const float* krow = qrow + C_;
    float q0 = qrow[lane], q1 = qrow[lane + 32];
    float k0 = krow[lane], k1 = krow[lane + 32];
    float sq = q0 * q0 + q1 * q1;
    float sk = k0 * k0 + k1 * k1;
    #pragma unroll
    for (int o = 16; o; o >>= 1) {
        sq += __shfl_xor_sync(0xFFFFFFFFu, sq, o);
        sk += __shfl_xor_sync(0xFFFFFFFFu, sk, o);
    }
    if (lane == 0) {
        g_rq[t * H_ + hh] = 0.125f * rsqrtf(fmaxf(sq, 1e-12f));
        g_rk[t * H_ + hh] = rsqrtf(fmaxf(sk, 1e-12f));
    }
}

__global__ void zero_attn_kernel()
{
    int i = blockIdx.x * blockDim.x + threadIdx.x;
    if (i < B_ * H_ * D_ * D_) g_attn[i] = 0.f;
}

// =================== attn[bh,d,e] = sum_n q~[n,d] * k~[n,e] ================
__global__ __launch_bounds__(256) void attn_qk_kernel()
{
    constexpr int TOKS = 32;
    __shared__ __align__(16) float qs[TOKS][68];
    __shared__ __align__(16) float ks[TOKS][68];
    const int tid = threadIdx.x;
    const int tx = tid & 15, ty = tid >> 4;
    const int bh = blockIdx.y, b = bh >> 3, hh = bh & 7;
    const int tok_base = blockIdx.x * 256;

    float acc[4][4];
    #pragma unroll
    for (int i = 0; i < 4; i++)
        #pragma unroll
        for (int j = 0; j < 4; j++) acc[i][j] = 0.f;

    for (int sub = 0; sub < 256; sub += TOKS) {
        #pragma unroll
        for (int it = 0; it < 2; it++) {
            int fid = tid + it * 256;
            int tl = fid >> 4, d4 = fid & 15;
            int t = b * N_ + tok_base + sub + tl;
            const float* base = g_qkv + (size_t)t * C3 + hh * D_ + d4 * 4;
            float rq = g_rq[t * H_ + hh];
            float rk = g_rk[t * H_ + hh];
            float4 qv = *(const float4*)base;
            float4 kv = *(const float4*)(base + C_);
            qv.x *= rq; qv.y *= rq; qv.z *= rq; qv.w *= rq;
            kv.x *= rk; kv.y *= rk; kv.z *= rk; kv.w *= rk;
            *(float4*)&qs[tl][d4 * 4] = qv;
            *(float4*)&ks[tl][d4 * 4] = kv;
        }
        __syncthreads();
        #pragma unroll 4
        for (int tok = 0; tok < TOKS; tok++) {
            float4 qd = *(const float4*)&qs[tok][ty * 4];
            float4 ke = *(const float4*)&ks[tok][tx * 4];
            float rd[4] = {qd.x, qd.y, qd.z, qd.w};
            float re[4] = {ke.x, ke.y, ke.z, ke.w};
            #pragma unroll
            for (int i = 0; i < 4; i++)
                #pragma unroll
                for (int j = 0; j < 4; j++)
                    acc[i][j] = fmaf(rd[i], re[j], acc[i][j]);
        }
        __syncthreads();
    }
    float* out = g_attn + (size_t)bh * D_ * D_;
    #pragma unroll
    for (int i = 0; i < 4; i++)
        #pragma unroll
        for (int j = 0; j < 4; j++)
            atomicAdd(&out[(ty * 4 + i) * D_ + tx * 4 + j], acc[i][j]);
}

__global__ __launch_bounds__(64) void softmax_kernel()
{
    __shared__ float red[64];
    float* p = g_attn + (size_t)blockIdx.x * 64;
    int t = threadIdx.x;
    float v = p[t];
    red[t] = v; __syncthreads();
    #pragma unroll
    for (int s = 32; s; s >>= 1) { if (t < s) red[t] = fmaxf(red[t], red[t + s]); __syncthreads(); }
    float m = red[0]; __syncthreads();
    float e = __expf(v - m);
    red[t] = e; __syncthreads();
    #pragma unroll
    for (int s = 32; s; s >>= 1) { if (t < s) red[t] += red[t + s]; __syncthreads(); }
    p[t] = e / red[0];
}

// ====== mid = v @ attn, written directly as split-bf16 A' for proj GEMM =====
__global__ __launch_bounds__(256) void v_attn_kernel()
{
    __shared__ __align__(16) float at[D_][D_];
    __shared__ __align__(16) float vs[D_][D_];
    const int tid = threadIdx.x;
    const int bh = blockIdx.y, b = bh >> 3, hh = bh & 7;
    const int tok0 = blockIdx.x * 64;

    const float* ap = g_attn + (size_t)bh * D_ * D_;
    #pragma unroll
    for (int it = 0; it < 4; it++) {
        int fid = tid + it * 256;
        ((float4*)at)[fid] = ((const float4*)ap)[fid];
    }
    #pragma unroll
    for (int it = 0; it < 4; it++) {
        int fid = tid + it * 256;
        int tl = fid >> 4, d4 = fid & 15;
        int t = b * N_ + tok0 + tl;
        *(float4*)&vs[tl][d4 * 4] =
            *(const float4*)(g_qkv + (size_t)t * C3 + 2 * C_ + hh * D_ + d4 * 4);
    }
    __syncthreads();

    const int rg = tid >> 4, cg = tid & 15;
    float acc[4][4];
    #pragma unroll
    for (int i = 0; i < 4; i++)
        #pragma unroll
        for (int j = 0; j < 4; j++) acc[i][j] = 0.f;

    #pragma unroll 8
    for (int d = 0; d < D_; d++) {
        float4 a4 = *(const float4*)&at[d][cg * 4];
        float ae[4] = {a4.x, a4.y, a4.z, a4.w};
        #pragma unroll
        for (int i = 0; i < 4; i++) {
            float va = vs[rg * 4 + i][d];
            #pragma unroll
            for (int j = 0; j < 4; j++)
                acc[i][j] = fmaf(va, ae[j], acc[i][j]);
        }
    }

    #pragma unroll
    for (int i = 0; i < 4; i++) {
        int t = b * N_ + tok0 + rg * 4 + i;
        float a0 = acc[i][0], a1 = acc[i][1], a2 = acc[i][2], a3 = acc[i][3];
        uint2 hi, lo;
        hi.x = packbf(a0, a1); hi.y = packbf(a2, a3);
        lo.x = packbf(a0 - bfr(a0), a1 - bfr(a1));
        lo.y = packbf(a2 - bfr(a2), a3 - bfr(a3));
        __nv_bfloat16* base = g_ms + (size_t)t * KS + hh * D_ + cg * 4;
        *(uint2*)(base)        = hi;
        *(uint2*)(base + 512)  = lo;
        *(uint2*)(base + 1024) = hi;
    }
}

// ================================ launch ===================================
extern "C" void kernel_launch(void* const* d_in, const int* in_sizes, int n_in,
                              void* d_out, int out_size)
{
    const float* x      = (const float*)d_in[0];
    const float* w_qkv  = (const float*)d_in[1];
    const float* b_qkv  = (const float*)d_in[2];
    const float* w_proj = (const float*)d_in[3];
    const float* b_proj = (const float*)d_in[4];
    float* out = (float*)d_out;

    __nv_bfloat16* xs; cudaGetSymbolAddress((void**)&xs, g_xs);
    __nv_bfloat16* ms; cudaGetSymbolAddress((void**)&ms, g_ms);
    __nv_bfloat16* wq; cudaGetSymbolAddress((void**)&wq, g_wq);
    __nv_bfloat16* wp; cudaGetSymbolAddress((void**)&wp, g_wp);
    float* qkv; cudaGetSymbolAddress((void**)&qkv, g_qkv);

    // prep: bf16 splits
    split_x_kernel<<<(MTOK * (C_ / 4)) / 256, 256>>>(x);
    split_w_kernel<<<dim3(C3 / 32, C_ / 32), 256>>>(w_qkv, wq, C3);
    split_w_kernel<<<dim3(C_ / 32, C_ / 32), 256>>>(w_proj, wp, C_);

    // qkv = x @ w_qkv + b_qkv  (mma.sync bf16, split precision)
    gemm_mma_kernel<<<dim3(C3 / 128, MTOK / 128), 256>>>(xs, wq, b_qkv, qkv, C3);

    norms_kernel<<<(MTOK * H_) / 8, 256>>>();
    zero_attn_kernel<<<(B_ * H_ * D_ * D_ + 255) / 256, 256>>>();
    attn_qk_kernel<<<dim3(N_ / 256, B_ * H_), 256>>>();
    softmax_kernel<<<B_ * H_ * D_, 64>>>();
    v_attn_kernel<<<dim3(N_ / 64, B_ * H_), 256>>>();

    // out = mid @ w_proj + b_proj
    gemm_mma_kernel<<<dim3(C_ / 128, MTOK / 128), 256>>>(ms, wp, b_proj, out, C_);
}

// round 4
// speedup vs baseline: 2.7853x; 1.4022x over previous
#include <cuda_runtime.h>
#include <cuda_fp16.h>
#include <math.h>
#include <stdint.h>

// Shapes (fixed): x[8,4096,512] f32, w_qkv[512,1536], b_qkv[1536],
// w_proj[512,512], b_proj[512], out[8,4096,512] f32.
constexpr int B_   = 8;
constexpr int N_   = 4096;
constexpr int C_   = 512;
constexpr int H_   = 8;
constexpr int D_   = 64;
constexpr int MTOK = B_ * N_;   // 32768
constexpr int C3   = 3 * C_;    // 1536
constexpr int KS   = 1024;      // fp16 2-term split-K': A=[hi|lo], B=[hi|hi]

// ------------------------- device scratch (static) -------------------------
__device__ __half g_xs[(size_t)MTOK * KS];   // split x      (A of qkv gemm)
__device__ __half g_ms[(size_t)MTOK * KS];   // split mid    (A of proj gemm)
__device__ __half g_wq[(size_t)C3 * KS];     // w_qkv^T hi dup  [n][k']
__device__ __half g_wp[(size_t)C_ * KS];     // w_proj^T hi dup [n][k']
__device__ float g_qkv[(size_t)MTOK * C3];   // qkv fp32 [tok][1536]
__device__ float g_attn[B_ * H_ * D_ * D_];

// ----------------------------- helpers ------------------------------------
__device__ __forceinline__ uint32_t smem_u32(const void* p) {
    uint32_t a;
    asm("{ .reg .u64 t; cvta.to.shared.u64 t, %1; cvt.u32.u64 %0, t; }"
        : "=r"(a) : "l"(p));
    return a;
}
__device__ __forceinline__ uint32_t packh(float a, float b) {
    __half2 p = __floats2half2_rn(a, b);
    return *(uint32_t*)&p;
}
__device__ __forceinline__ float hfr(float v) {  // value after fp16 round
    return __half2float(__float2half_rn(v));
}

#define CP_ASYNC16(dst_u32, src_ptr) \
    asm volatile("cp.async.cg.shared.global [%0], [%1], 16;" \
        :: "r"(dst_u32), "l"(src_ptr))
#define CP_COMMIT()  asm volatile("cp.async.commit_group;")
#define CP_WAIT0()   asm volatile("cp.async.wait_group 0;" ::: "memory")

__device__ __forceinline__ void ldmatrix_x4(uint32_t* r, uint32_t addr) {
    asm volatile("ldmatrix.sync.aligned.m8n8.x4.shared.b16 {%0,%1,%2,%3}, [%4];"
        : "=r"(r[0]), "=r"(r[1]), "=r"(r[2]), "=r"(r[3]) : "r"(addr));
}
__device__ __forceinline__ void mma_f16(float* c, const uint32_t* a,
                                        uint32_t b0, uint32_t b1) {
    asm volatile(
        "mma.sync.aligned.m16n8k16.row.col.f32.f16.f16.f32 "
        "{%0,%1,%2,%3}, {%4,%5,%6,%7}, {%8,%9}, {%0,%1,%2,%3};"
        : "+f"(c[0]), "+f"(c[1]), "+f"(c[2]), "+f"(c[3])
        : "r"(a[0]), "r"(a[1]), "r"(a[2]), "r"(a[3]), "r"(b0), "r"(b1));
}

// =========================== split prep kernels ============================
// g_xs[t][0:512)=hi(x), [512:1024)=lo(x)
__global__ __launch_bounds__(256) void split_x_kernel(const float* __restrict__ x)
{
    size_t fid = (size_t)blockIdx.x * 256 + threadIdx.x;  // MTOK*128 float4s
    size_t t = fid >> 7;
    int c4 = (int)(fid & 127);
    float4 v = ((const float4*)x)[fid];
    float hx = hfr(v.x), hy = hfr(v.y), hz = hfr(v.z), hw = hfr(v.w);
    uint2 hi, lo;
    hi.x = packh(v.x, v.y); hi.y = packh(v.z, v.w);
    lo.x = packh(v.x - hx, v.y - hy); lo.y = packh(v.z - hz, v.w - hw);
    __half* base = g_xs + t * KS + c4 * 4;
    *(uint2*)(base)       = hi;
    *(uint2*)(base + 512) = lo;
}

// W[512][Ntot] -> out[n][k'] transposed: hi at [0:512) and duplicated at [512:1024)
__global__ __launch_bounds__(256) void split_w_kernel(const float* __restrict__ W,
                                                      __half* __restrict__ out,
                                                      int Ntot)
{
    __shared__ float tile[32][33];
    int n0 = blockIdx.x * 32, k0 = blockIdx.y * 32;
    int tx = threadIdx.x & 31, ty = threadIdx.x >> 5;  // ty 0..7
    #pragma unroll
    for (int i = 0; i < 32; i += 8)
        tile[ty + i][tx] = W[(size_t)(k0 + ty + i) * Ntot + n0 + tx];
    __syncthreads();
    #pragma unroll
    for (int i = 0; i < 32; i += 8) {
        float v = tile[tx][ty + i];              // = W[k0+tx][n0+ty+i]
        __half h = __float2half_rn(v);
        __half* o = out + (size_t)(n0 + ty + i) * KS + k0 + tx;
        o[0] = h; o[512] = h;
    }
}

// ================== mma.sync fp16 GEMM, 128x128 CTA tile ===================
// C[M,Ntot] = Asplit[M,1024] @ Bsplit[Ntot,1024]^T + bias, fp32 out.
// 8 warps in 2x4 grid; warp tile 64x32; BK=32; double-buffered cp.async.
constexpr int NKC = KS / 32;       // 32 k-chunks
constexpr int APITCH = 40;         // fp16 elems per smem row (80B: conflict-free)

__global__ __launch_bounds__(256, 2) void gemm_mma_kernel(
    const __half* __restrict__ A, const __half* __restrict__ Bm,
    const float* __restrict__ bias, float* __restrict__ C, int Ntot)
{
    __shared__ __align__(16) __half As[2][128][APITCH];
    __shared__ __align__(16) __half Bs[2][128][APITCH];

    const int tid  = threadIdx.x;
    const int lane = tid & 31;
    const int wid  = tid >> 5;
    const int wr   = wid & 1;     // warp row (0-1): 64 rows each
    const int wc   = wid >> 1;    // warp col (0-3): 32 cols each
    const size_t rowA0 = (size_t)blockIdx.y * 128;
    const size_t rowB0 = (size_t)blockIdx.x * 128;

    const __half* Abase = A + rowA0 * KS;
    const __half* Bbase = Bm + rowB0 * KS;

    uint32_t as_base = smem_u32(&As[0][0][0]);
    uint32_t bs_base = smem_u32(&Bs[0][0][0]);
    constexpr uint32_t BUF_BYTES = 128 * APITCH * 2;  // 10240

    auto stage_copy = [&](int kc, int buf) {
        #pragma unroll
        for (int i = 0; i < 2; i++) {
            int idx = tid + i * 256;           // 0..511
            int r = idx >> 2, c16 = idx & 3;   // c16*8 fp16 offset
            const __half* g = Abase + (size_t)r * KS + kc * 32 + c16 * 8;
            uint32_t d = as_base + buf * BUF_BYTES + (uint32_t)(r * 80 + c16 * 16);
            CP_ASYNC16(d, g);
        }
        #pragma unroll
        for (int i = 0; i < 2; i++) {
            int idx = tid + i * 256;
            int r = idx >> 2, c16 = idx & 3;
            const __half* g = Bbase + (size_t)r * KS + kc * 32 + c16 * 8;
            uint32_t d = bs_base + buf * BUF_BYTES + (uint32_t)(r * 80 + c16 * 16);
            CP_ASYNC16(d, g);
        }
        CP_COMMIT();
    };

    float acc[4][4][4];
    #pragma unroll
    for (int i = 0; i < 4; i++)
        #pragma unroll
        for (int j = 0; j < 4; j++)
            #pragma unroll
            for (int k = 0; k < 4; k++) acc[i][j][k] = 0.f;

    // ldmatrix source addresses
    const int a_row = wr * 64 + (lane & 7) + ((lane >> 3) & 1) * 8;
    const int a_k8  = ((lane >> 4) & 1) * 8;
    const int b_row = wc * 32 + (lane & 7) + ((lane >> 4) & 1) * 8;
    const int b_k8  = ((lane >> 3) & 1) * 8;

    stage_copy(0, 0);
    CP_WAIT0();
    __syncthreads();

    #pragma unroll 1
    for (int kc = 0; kc < NKC; kc++) {
        const int buf = kc & 1;
        if (kc + 1 < NKC) stage_copy(kc + 1, buf ^ 1);

        const uint32_t ab = as_base + buf * BUF_BYTES;
        const uint32_t bb = bs_base + buf * BUF_BYTES;
        #pragma unroll
        for (int ks = 0; ks < 2; ks++) {
            uint32_t afr[4][4];
            #pragma unroll
            for (int mi = 0; mi < 4; mi++)
                ldmatrix_x4(afr[mi],
                    ab + (uint32_t)((a_row + mi * 16) * 80 + (ks * 16 + a_k8) * 2));
            uint32_t bfrg[2][4];
            #pragma unroll
            for (int nj2 = 0; nj2 < 2; nj2++)
                ldmatrix_x4(bfrg[nj2],
                    bb + (uint32_t)((b_row + nj2 * 16) * 80 + (ks * 16 + b_k8) * 2));
            #pragma unroll
            for (int mi = 0; mi < 4; mi++) {
                #pragma unroll
                for (int nj = 0; nj < 4; nj++) {
                    uint32_t b0 = bfrg[nj >> 1][(nj & 1) * 2];
                    uint32_t b1 = bfrg[nj >> 1][(nj & 1) * 2 + 1];
                    mma_f16(acc[mi][nj], afr[mi], b0, b1);
                }
            }
        }
        if (kc + 1 < NKC) CP_WAIT0();
        __syncthreads();
    }

    // epilogue: direct stores + bias
    #pragma unroll
    for (int mi = 0; mi < 4; mi++) {
        size_t r0 = rowA0 + wr * 64 + mi * 16 + (lane >> 2);
        size_t r1 = r0 + 8;
        #pragma unroll
        for (int nj = 0; nj < 4; nj++) {
            size_t col = rowB0 + wc * 32 + nj * 8 + (lane & 3) * 2;
            float b0 = __ldg(&bias[col]), b1 = __ldg(&bias[col + 1]);
            float2 v0 = {acc[mi][nj][0] + b0, acc[mi][nj][1] + b1};
            float2 v1 = {acc[mi][nj][2] + b0, acc[mi][nj][3] + b1};
            *(float2*)(C + r0 * (size_t)Ntot + col) = v0;
            *(float2*)(C + r1 * (size_t)Ntot + col) = v1;
        }
    }
}

__global__ void zero_attn_kernel()
{
    int i = blockIdx.x * blockDim.x + threadIdx.x;
    if (i < B_ * H_ * D_ * D_) g_attn[i] = 0.f;
}

// ========== attn[bh,d,e] = sum_n q~[n,d] k~[n,e], norms fused inline =======
__global__ __launch_bounds__(256) void attn_qk_kernel()
{
    constexpr int TOKS = 32;
    __shared__ __align__(16) float qs[TOKS][68];
    __shared__ __align__(16) float ks[TOKS][68];
    const int tid = threadIdx.x;
    const int tx = tid & 15, ty = tid >> 4;
    const int bh = blockIdx.y, b = bh >> 3, hh = bh & 7;
    const int tok_base = blockIdx.x * 256;

    float acc[4][4];
    #pragma unroll
    for (int i = 0; i < 4; i++)
        #pragma unroll
        for (int j = 0; j < 4; j++) acc[i][j] = 0.f;

    for (int sub = 0; sub < 256; sub += TOKS) {
        #pragma unroll
        for (int it = 0; it < 2; it++) {
            int fid = tid + it * 256;
            int tl = fid >> 4, d4 = fid & 15;
            int t = b * N_ + tok_base + sub + tl;
            const float* base = g_qkv + (size_t)t * C3 + hh * D_ + d4 * 4;
            float4 qv = *(const float4*)base;
            float4 kv = *(const float4*)(base + C_);
            // fused l2-norm: reduce sumsq across the 16 lanes of this row
            float sq = qv.x * qv.x + qv.y * qv.y + qv.z * qv.z + qv.w * qv.w;
            float sk = kv.x * kv.x + kv.y * kv.y + kv.z * kv.z + kv.w * kv.w;
            #pragma unroll
            for (int o = 8; o; o >>= 1) {
                sq += __shfl_xor_sync(0xFFFFFFFFu, sq, o);
                sk += __shfl_xor_sync(0xFFFFFFFFu, sk, o);
            }
            float rq = 0.125f * rsqrtf(fmaxf(sq, 1e-12f));  // includes d^-0.5
            float rk = rsqrtf(fmaxf(sk, 1e-12f));
            qv.x *= rq; qv.y *= rq; qv.z *= rq; qv.w *= rq;
            kv.x *= rk; kv.y *= rk; kv.z *= rk; kv.w *= rk;
            *(float4*)&qs[tl][d4 * 4] = qv;
            *(float4*)&ks[tl][d4 * 4] = kv;
        }
        __syncthreads();
        #pragma unroll 4
        for (int tok = 0; tok < TOKS; tok++) {
            float4 qd = *(const float4*)&qs[tok][ty * 4];
            float4 ke = *(const float4*)&ks[tok][tx * 4];
            float rd[4] = {qd.x, qd.y, qd.z, qd.w};
            float re[4] = {ke.x, ke.y, ke.z, ke.w};
            #pragma unroll
            for (int i = 0; i < 4; i++)
                #pragma unroll
                for (int j = 0; j < 4; j++)
                    acc[i][j] = fmaf(rd[i], re[j], acc[i][j]);
        }
        __syncthreads();
    }
    float* out = g_attn + (size_t)bh * D_ * D_;
    #pragma unroll
    for (int i = 0; i < 4; i++)
        #pragma unroll
        for (int j = 0; j < 4; j++)
            atomicAdd(&out[(ty * 4 + i) * D_ + tx * 4 + j], acc[i][j]);
}

__global__ __launch_bounds__(64) void softmax_kernel()
{
    __shared__ float red[64];
    float* p = g_attn + (size_t)blockIdx.x * 64;
    int t = threadIdx.x;
    float v = p[t];
    red[t] = v; __syncthreads();
    #pragma unroll
    for (int s = 32; s; s >>= 1) { if (t < s) red[t] = fmaxf(red[t], red[t + s]); __syncthreads(); }
    float m = red[0]; __syncthreads();
    float e = __expf(v - m);
    red[t] = e; __syncthreads();
    #pragma unroll
    for (int s = 32; s; s >>= 1) { if (t < s) red[t] += red[t + s]; __syncthreads(); }
    p[t] = e / red[0];
}

// ====== mid = v @ attn, written directly as split-fp16 A' for proj GEMM =====
__global__ __launch_bounds__(256) void v_attn_kernel()
{
    __shared__ __align__(16) float at[D_][D_];
    __shared__ __align__(16) float vs[D_][D_];
    const int tid = threadIdx.x;
    const int bh = blockIdx.y, b = bh >> 3, hh = bh & 7;
    const int tok0 = blockIdx.x * 64;

    const float* ap = g_attn + (size_t)bh * D_ * D_;
    #pragma unroll
    for (int it = 0; it < 4; it++) {
        int fid = tid + it * 256;
        ((float4*)at)[fid] = ((const float4*)ap)[fid];
    }
    #pragma unroll
    for (int it = 0; it < 4; it++) {
        int fid = tid + it * 256;
        int tl = fid >> 4, d4 = fid & 15;
        int t = b * N_ + tok0 + tl;
        *(float4*)&vs[tl][d4 * 4] =
            *(const float4*)(g_qkv + (size_t)t * C3 + 2 * C_ + hh * D_ + d4 * 4);
    }
    __syncthreads();

    const int rg = tid >> 4, cg = tid & 15;
    float acc[4][4];
    #pragma unroll
    for (int i = 0; i < 4; i++)
        #pragma unroll
        for (int j = 0; j < 4; j++) acc[i][j] = 0.f;

    #pragma unroll 8
    for (int d = 0; d < D_; d++) {
        float4 a4 = *(const float4*)&at[d][cg * 4];
        float ae[4] = {a4.x, a4.y, a4.z, a4.w};
        #pragma unroll
        for (int i = 0; i < 4; i++) {
            float va = vs[rg * 4 + i][d];
            #pragma unroll
            for (int j = 0; j < 4; j++)
                acc[i][j] = fmaf(va, ae[j], acc[i][j]);
        }
    }

    #pragma unroll
    for (int i = 0; i < 4; i++) {
        int t = b * N_ + tok0 + rg * 4 + i;
        float a0 = acc[i][0], a1 = acc[i][1], a2 = acc[i][2], a3 = acc[i][3];
        uint2 hi, lo;
        hi.x = packh(a0, a1); hi.y = packh(a2, a3);
        lo.x = packh(a0 - hfr(a0), a1 - hfr(a1));
        lo.y = packh(a2 - hfr(a2), a3 - hfr(a3));
        __half* base = g_ms + (size_t)t * KS + hh * D_ + cg * 4;
        *(uint2*)(base)       = hi;
        *(uint2*)(base + 512) = lo;
    }
}

// ================================ launch ===================================
extern "C" void kernel_launch(void* const* d_in, const int* in_sizes, int n_in,
                              void* d_out, int out_size)
{
    const float* x      = (const float*)d_in[0];
    const float* w_qkv  = (const float*)d_in[1];
    const float* b_qkv  = (const float*)d_in[2];
    const float* w_proj = (const float*)d_in[3];
    const float* b_proj = (const float*)d_in[4];
    float* out = (float*)d_out;

    __half* xs; cudaGetSymbolAddress((void**)&xs, g_xs);
    __half* ms; cudaGetSymbolAddress((void**)&ms, g_ms);
    __half* wq; cudaGetSymbolAddress((void**)&wq, g_wq);
    __half* wp; cudaGetSymbolAddress((void**)&wp, g_wp);
    float* qkv; cudaGetSymbolAddress((void**)&qkv, g_qkv);

    // prep: fp16 splits
    split_x_kernel<<<(MTOK * (C_ / 4)) / 256, 256>>>(x);
    split_w_kernel<<<dim3(C3 / 32, C_ / 32), 256>>>(w_qkv, wq, C3);
    split_w_kernel<<<dim3(C_ / 32, C_ / 32), 256>>>(w_proj, wp, C_);

    // qkv = x @ w_qkv + b_qkv  (mma.sync fp16, 2-term split)
    gemm_mma_kernel<<<dim3(C3 / 128, MTOK / 128), 256>>>(xs, wq, b_qkv, qkv, C3);

    zero_attn_kernel<<<(B_ * H_ * D_ * D_ + 255) / 256, 256>>>();
    attn_qk_kernel<<<dim3(N_ / 256, B_ * H_), 256>>>();
    softmax_kernel<<<B_ * H_ * D_, 64>>>();
    v_attn_kernel<<<dim3(N_ / 64, B_ * H_), 256>>>();

    // out = mid @ w_proj + b_proj
    gemm_mma_kernel<<<dim3(C_ / 128, MTOK / 128), 256>>>(ms, wp, b_proj, out, C_);
}

// round 6
// speedup vs baseline: 3.0753x; 1.1041x over previous
#include <cuda_runtime.h>
#include <cuda_fp16.h>
#include <math.h>
#include <stdint.h>

// Shapes (fixed): x[8,4096,512] f32, w_qkv[512,1536], b_qkv[1536],
// w_proj[512,512], b_proj[512], out[8,4096,512] f32.
constexpr int B_   = 8;
constexpr int N_   = 4096;
constexpr int C_   = 512;
constexpr int H_   = 8;
constexpr int D_   = 64;
constexpr int MTOK = B_ * N_;   // 32768
constexpr int C3   = 3 * C_;    // 1536
constexpr int KA   = 1024;      // A split width: [hi(512) | lo(512)]
constexpr int KB   = 512;       // B width (hi only; reused for both A parts)

// ------------------------- device scratch (static) -------------------------
__device__ __half g_xs[(size_t)MTOK * KA];   // split x      (A of qkv gemm)
__device__ __half g_ms[(size_t)MTOK * KA];   // split mid    (A of proj gemm)
__device__ __half g_wq[(size_t)C3 * KB];     // w_qkv^T hi   [n][k]
__device__ __half g_wp[(size_t)C_ * KB];     // w_proj^T hi  [n][k]
__device__ float g_qkv[(size_t)MTOK * C3];   // qkv fp32 [tok][1536]
__device__ float g_attn[B_ * H_ * D_ * D_];

// ----------------------------- helpers ------------------------------------
__device__ __forceinline__ uint32_t smem_u32(const void* p) {
    uint32_t a;
    asm("{ .reg .u64 t; cvta.to.shared.u64 t, %1; cvt.u32.u64 %0, t; }"
        : "=r"(a) : "l"(p));
    return a;
}
__device__ __forceinline__ uint32_t packh(float a, float b) {
    __half2 p = __floats2half2_rn(a, b);
    return *(uint32_t*)&p;
}
__device__ __forceinline__ float hfr(float v) {  // value after fp16 round
    return __half2float(__float2half_rn(v));
}

#define CP_ASYNC16(dst_u32, src_ptr) \
    asm volatile("cp.async.cg.shared.global [%0], [%1], 16;" \
        :: "r"(dst_u32), "l"(src_ptr))
#define CP_COMMIT()  asm volatile("cp.async.commit_group;")
#define CP_WAIT0()   asm volatile("cp.async.wait_group 0;" ::: "memory")

__device__ __forceinline__ void ldmatrix_x4(uint32_t* r, uint32_t addr) {
    asm volatile("ldmatrix.sync.aligned.m8n8.x4.shared.b16 {%0,%1,%2,%3}, [%4];"
        : "=r"(r[0]), "=r"(r[1]), "=r"(r[2]), "=r"(r[3]) : "r"(addr));
}
__device__ __forceinline__ void mma_f16(float* c, const uint32_t* a,
                                        uint32_t b0, uint32_t b1) {
    asm volatile(
        "mma.sync.aligned.m16n8k16.row.col.f32.f16.f16.f32 "
        "{%0,%1,%2,%3}, {%4,%5,%6,%7}, {%8,%9}, {%0,%1,%2,%3};"
        : "+f"(c[0]), "+f"(c[1]), "+f"(c[2]), "+f"(c[3])
        : "r"(a[0]), "r"(a[1]), "r"(a[2]), "r"(a[3]), "r"(b0), "r"(b1));
}

// =========================== split prep kernels ============================
// g_xs[t][0:512)=hi(x), [512:1024)=lo(x)
__global__ __launch_bounds__(256) void split_x_kernel(const float* __restrict__ x)
{
    size_t fid = (size_t)blockIdx.x * 256 + threadIdx.x;  // MTOK*128 float4s
    size_t t = fid >> 7;
    int c4 = (int)(fid & 127);
    float4 v = ((const float4*)x)[fid];
    float hx = hfr(v.x), hy = hfr(v.y), hz = hfr(v.z), hw = hfr(v.w);
    uint2 hi, lo;
    hi.x = packh(v.x, v.y); hi.y = packh(v.z, v.w);
    lo.x = packh(v.x - hx, v.y - hy); lo.y = packh(v.z - hz, v.w - hw);
    __half* base = g_xs + t * KA + c4 * 4;
    *(uint2*)(base)       = hi;
    *(uint2*)(base + 512) = lo;
}

// W[512][Ntot] -> out[n][k] transposed fp16 (hi only)
__global__ __launch_bounds__(256) void split_w_kernel(const float* __restrict__ W,
                                                      __half* __restrict__ out,
                                                      int Ntot)
{
    __shared__ float tile[32][33];
    int n0 = blockIdx.x * 32, k0 = blockIdx.y * 32;
    int tx = threadIdx.x & 31, ty = threadIdx.x >> 5;  // ty 0..7
    #pragma unroll
    for (int i = 0; i < 32; i += 8)
        tile[ty + i][tx] = W[(size_t)(k0 + ty + i) * Ntot + n0 + tx];
    __syncthreads();
    #pragma unroll
    for (int i = 0; i < 32; i += 8) {
        float v = tile[tx][ty + i];              // = W[k0+tx][n0+ty+i]
        out[(size_t)(n0 + ty + i) * KB + k0 + tx] = __float2half_rn(v);
    }
}

// ================== mma.sync fp16 GEMM, 128x128 CTA tile ===================
// C[M,Ntot] = (hiA+loA)[M,512] @ hiB[Ntot,512]^T + bias, fp32 out.
// A is stored split [hi|lo]; B smem tile is loaded ONCE per k-chunk and its
// fragments are reused for both A parts. BK=32, 16 chunks, double-buffered.
constexpr int NKC    = KB / 32;                 // 16 k-chunks
constexpr int APITCH = 40;                      // fp16/row (80B, conflict-free)
constexpr int TILE_B = 128 * APITCH * 2;        // 10240 bytes per tile
constexpr int STAGE_B = 3 * TILE_B;             // Ahi + Alo + B
constexpr int GEMM_SMEM = 2 * STAGE_B;          // 61440 bytes

__global__ __launch_bounds__(256, 2) void gemm_mma_kernel(
    const __half* __restrict__ A, const __half* __restrict__ Bm,
    const float* __restrict__ bias, float* __restrict__ C, int Ntot)
{
    extern __shared__ __align__(16) __half smem[];

    const int tid  = threadIdx.x;
    const int lane = tid & 31;
    const int wid  = tid >> 5;
    const int wr   = wid & 1;     // warp row (0-1): 64 rows each
    const int wc   = wid >> 1;    // warp col (0-3): 32 cols each
    const size_t rowA0 = (size_t)blockIdx.y * 128;
    const size_t rowB0 = (size_t)blockIdx.x * 128;

    const __half* Abase = A + rowA0 * KA;
    const __half* Bbase = Bm + rowB0 * KB;

    const uint32_t s_base = smem_u32(smem);

    // per-thread copy coordinates: idx in [0,512), r=row, c16=16B chunk
    const int cr0 = tid >> 2, cc0 = (tid & 3);          // idx = tid
    const int cr1 = (tid + 256) >> 2, cc1 = (tid + 256) & 3;

    float acc[4][4][4];
    #pragma unroll
    for (int i = 0; i < 4; i++)
        #pragma unroll
        for (int j = 0; j < 4; j++)
            #pragma unroll
            for (int k = 0; k < 4; k++) acc[i][j][k] = 0.f;

    // ldmatrix source coordinates
    const int a_row = wr * 64 + (lane & 7) + ((lane >> 3) & 1) * 8;
    const int a_k8  = ((lane >> 4) & 1) * 8;
    const int b_row = wc * 32 + (lane & 7) + ((lane >> 4) & 1) * 8;
    const int b_k8  = ((lane >> 3) & 1) * 8;

    // ---- prologue: stage chunk 0 into buffer 0 ----
    {
        const uint32_t st = s_base;
        uint32_t so0 = (uint32_t)(cr0 * 80 + cc0 * 16);
        uint32_t so1 = (uint32_t)(cr1 * 80 + cc1 * 16);
        const __half* ga0 = Abase + (size_t)cr0 * KA + cc0 * 8;
        const __half* ga1 = Abase + (size_t)cr1 * KA + cc1 * 8;
        CP_ASYNC16(st + so0, ga0);
        CP_ASYNC16(st + so1, ga1);
        CP_ASYNC16(st + TILE_B + so0, ga0 + 512);
        CP_ASYNC16(st + TILE_B + so1, ga1 + 512);
        const __half* gb0 = Bbase + (size_t)cr0 * KB + cc0 * 8;
        const __half* gb1 = Bbase + (size_t)cr1 * KB + cc1 * 8;
        CP_ASYNC16(st + 2 * TILE_B + so0, gb0);
        CP_ASYNC16(st + 2 * TILE_B + so1, gb1);
        CP_COMMIT();
    }
    CP_WAIT0();
    __syncthreads();

    #pragma unroll 1
    for (int kc = 0; kc < NKC; kc++) {
        const int buf = kc & 1;
        if (kc + 1 < NKC) {
            const uint32_t st = s_base + (buf ^ 1) * STAGE_B;
            const int ko = (kc + 1) * 32;
            uint32_t so0 = (uint32_t)(cr0 * 80 + cc0 * 16);
            uint32_t so1 = (uint32_t)(cr1 * 80 + cc1 * 16);
            const __half* ga0 = Abase + (size_t)cr0 * KA + ko + cc0 * 8;
            const __half* ga1 = Abase + (size_t)cr1 * KA + ko + cc1 * 8;
            CP_ASYNC16(st + so0, ga0);
            CP_ASYNC16(st + so1, ga1);
            CP_ASYNC16(st + TILE_B + so0, ga0 + 512);
            CP_ASYNC16(st + TILE_B + so1, ga1 + 512);
            const __half* gb0 = Bbase + (size_t)cr0 * KB + ko + cc0 * 8;
            const __half* gb1 = Bbase + (size_t)cr1 * KB + ko + cc1 * 8;
            CP_ASYNC16(st + 2 * TILE_B + so0, gb0);
            CP_ASYNC16(st + 2 * TILE_B + so1, gb1);
            CP_COMMIT();
        }

        const uint32_t st = s_base + buf * STAGE_B;
        const uint32_t bb = st + 2 * TILE_B;
        #pragma unroll
        for (int ks = 0; ks < 2; ks++) {
            uint32_t bfrg[2][4];
            #pragma unroll
            for (int nj2 = 0; nj2 < 2; nj2++)
                ldmatrix_x4(bfrg[nj2],
                    bb + (uint32_t)((b_row + nj2 * 16) * 80 + (ks * 16 + b_k8) * 2));
            #pragma unroll
            for (int part = 0; part < 2; part++) {
                const uint32_t ab = st + part * TILE_B;
                uint32_t afr[4][4];
                #pragma unroll
                for (int mi = 0; mi < 4; mi++)
                    ldmatrix_x4(afr[mi],
                        ab + (uint32_t)((a_row + mi * 16) * 80 + (ks * 16 + a_k8) * 2));
                #pragma unroll
                for (int mi = 0; mi < 4; mi++) {
                    #pragma unroll
                    for (int nj = 0; nj < 4; nj++) {
                        uint32_t b0 = bfrg[nj >> 1][(nj & 1) * 2];
                        uint32_t b1 = bfrg[nj >> 1][(nj & 1) * 2 + 1];
                        mma_f16(acc[mi][nj], afr[mi], b0, b1);
                    }
                }
            }
        }
        if (kc + 1 < NKC) CP_WAIT0();
        __syncthreads();
    }

    // epilogue: direct stores + bias
    #pragma unroll
    for (int mi = 0; mi < 4; mi++) {
        size_t r0 = rowA0 + wr * 64 + mi * 16 + (lane >> 2);
        size_t r1 = r0 + 8;
        #pragma unroll
        for (int nj = 0; nj < 4; nj++) {
            size_t col = rowB0 + wc * 32 + nj * 8 + (lane & 3) * 2;
            float b0 = __ldg(&bias[col]), b1 = __ldg(&bias[col + 1]);
            float2 v0 = {acc[mi][nj][0] + b0, acc[mi][nj][1] + b1};
            float2 v1 = {acc[mi][nj][2] + b0, acc[mi][nj][3] + b1};
            *(float2*)(C + r0 * (size_t)Ntot + col) = v0;
            *(float2*)(C + r1 * (size_t)Ntot + col) = v1;
        }
    }
}

__global__ void zero_attn_kernel()
{
    int i = blockIdx.x * blockDim.x + threadIdx.x;
    if (i < B_ * H_ * D_ * D_) g_attn[i] = 0.f;
}

// ========== attn[bh,d,e] = sum_n q~[n,d] k~[n,e], norms fused inline =======
__global__ __launch_bounds__(256) void attn_qk_kernel()
{
    constexpr int TOKS = 32;
    __shared__ __align__(16) float qs[TOKS][68];
    __shared__ __align__(16) float ks[TOKS][68];
    const int tid = threadIdx.x;
    const int tx = tid & 15, ty = tid >> 4;
    const int bh = blockIdx.y, b = bh >> 3, hh = bh & 7;
    const int tok_base = blockIdx.x * 256;

    float acc[4][4];
    #pragma unroll
    for (int i = 0; i < 4; i++)
        #pragma unroll
        for (int j = 0; j < 4; j++) acc[i][j] = 0.f;

    for (int sub = 0; sub < 256; sub += TOKS) {
        #pragma unroll
        for (int it = 0; it < 2; it++) {
            int fid = tid + it * 256;
            int tl = fid >> 4, d4 = fid & 15;
            int t = b * N_ + tok_base + sub + tl;
            const float* base = g_qkv + (size_t)t * C3 + hh * D_ + d4 * 4;
            float4 qv = *(const float4*)base;
            float4 kv = *(const float4*)(base + C_);
            float sq = qv.x * qv.x + qv.y * qv.y + qv.z * qv.z + qv.w * qv.w;
            float sk = kv.x * kv.x + kv.y * kv.y + kv.z * kv.z + kv.w * kv.w;
            #pragma unroll
            for (int o = 8; o; o >>= 1) {
                sq += __shfl_xor_sync(0xFFFFFFFFu, sq, o);
                sk += __shfl_xor_sync(0xFFFFFFFFu, sk, o);
            }
            float rq = 0.125f * rsqrtf(fmaxf(sq, 1e-12f));  // includes d^-0.5
            float rk = rsqrtf(fmaxf(sk, 1e-12f));
            qv.x *= rq; qv.y *= rq; qv.z *= rq; qv.w *= rq;
            kv.x *= rk; kv.y *= rk; kv.z *= rk; kv.w *= rk;
            *(float4*)&qs[tl][d4 * 4] = qv;
            *(float4*)&ks[tl][d4 * 4] = kv;
        }
        __syncthreads();
        #pragma unroll 4
        for (int tok = 0; tok < TOKS; tok++) {
            float4 qd = *(const float4*)&qs[tok][ty * 4];
            float4 ke = *(const float4*)&ks[tok][tx * 4];
            float rd[4] = {qd.x, qd.y, qd.z, qd.w};
            float re[4] = {ke.x, ke.y, ke.z, ke.w};
            #pragma unroll
            for (int i = 0; i < 4; i++)
                #pragma unroll
                for (int j = 0; j < 4; j++)
                    acc[i][j] = fmaf(rd[i], re[j], acc[i][j]);
        }
        __syncthreads();
    }
    float* out = g_attn + (size_t)bh * D_ * D_;
    #pragma unroll
    for (int i = 0; i < 4; i++)
        #pragma unroll
        for (int j = 0; j < 4; j++)
            atomicAdd(&out[(ty * 4 + i) * D_ + tx * 4 + j], acc[i][j]);
}

__global__ __launch_bounds__(64) void softmax_kernel()
{
    __shared__ float red[64];
    float* p = g_attn + (size_t)blockIdx.x * 64;
    int t = threadIdx.x;
    float v = p[t];
    red[t] = v; __syncthreads();
    #pragma unroll
    for (int s = 32; s; s >>= 1) { if (t < s) red[t] = fmaxf(red[t], red[t + s]); __syncthreads(); }
    float m = red[0]; __syncthreads();
    float e = __expf(v - m);
    red[t] = e; __syncthreads();
    #pragma unroll
    for (int s = 32; s; s >>= 1) { if (t < s) red[t] += red[t + s]; __syncthreads(); }
    p[t] = e / red[0];
}

// ====== mid = v @ attn, written directly as split-fp16 A' for proj GEMM =====
__global__ __launch_bounds__(256) void v_attn_kernel()
{
    __shared__ __align__(16) float at[D_][D_];
    __shared__ __align__(16) float vs[D_][D_];
    const int tid = threadIdx.x;
    const int bh = blockIdx.y, b = bh >> 3, hh = bh & 7;
    const int tok0 = blockIdx.x * 64;

    const float* ap = g_attn + (size_t)bh * D_ * D_;
    #pragma unroll
    for (int it = 0; it < 4; it++) {
        int fid = tid + it * 256;
        ((float4*)at)[fid] = ((const float4*)ap)[fid];
    }
    #pragma unroll
    for (int it = 0; it < 4; it++) {
        int fid = tid + it * 256;
        int tl = fid >> 4, d4 = fid & 15;
        int t = b * N_ + tok0 + tl;
        *(float4*)&vs[tl][d4 * 4] =
            *(const float4*)(g_qkv + (size_t)t * C3 + 2 * C_ + hh * D_ + d4 * 4);
    }
    __syncthreads();

    const int rg = tid >> 4, cg = tid & 15;
    float acc[4][4];
    #pragma unroll
    for (int i = 0; i < 4; i++)
        #pragma unroll
        for (int j = 0; j < 4; j++) acc[i][j] = 0.f;

    #pragma unroll 8
    for (int d = 0; d < D_; d++) {
        float4 a4 = *(const float4*)&at[d][cg * 4];
        float ae[4] = {a4.x, a4.y, a4.z, a4.w};
        #pragma unroll
        for (int i = 0; i < 4; i++) {
            float va = vs[rg * 4 + i][d];
            #pragma unroll
            for (int j = 0; j < 4; j++)
                acc[i][j] = fmaf(va, ae[j], acc[i][j]);
        }
    }

    #pragma unroll
    for (int i = 0; i < 4; i++) {
        int t = b * N_ + tok0 + rg * 4 + i;
        float a0 = acc[i][0], a1 = acc[i][1], a2 = acc[i][2], a3 = acc[i][3];
        uint2 hi, lo;
        hi.x = packh(a0, a1); hi.y = packh(a2, a3);
        lo.x = packh(a0 - hfr(a0), a1 - hfr(a1));
        lo.y = packh(a2 - hfr(a2), a3 - hfr(a3));
        __half* base = g_ms + (size_t)t * KA + hh * D_ + cg * 4;
        *(uint2*)(base)       = hi;
        *(uint2*)(base + 512) = lo;
    }
}

// ================================ launch ===================================
extern "C" void kernel_launch(void* const* d_in, const int* in_sizes, int n_in,
                              void* d_out, int out_size)
{
    const float* x      = (const float*)d_in[0];
    const float* w_qkv  = (const float*)d_in[1];
    const float* b_qkv  = (const float*)d_in[2];
    const float* w_proj = (const float*)d_in[3];
    const float* b_proj = (const float*)d_in[4];
    float* out = (float*)d_out;

    __half* xs; cudaGetSymbolAddress((void**)&xs, g_xs);
    __half* ms; cudaGetSymbolAddress((void**)&ms, g_ms);
    __half* wq; cudaGetSymbolAddress((void**)&wq, g_wq);
    __half* wp; cudaGetSymbolAddress((void**)&wp, g_wp);
    float* qkv; cudaGetSymbolAddress((void**)&qkv, g_qkv);

    cudaFuncSetAttribute(gemm_mma_kernel,
                         cudaFuncAttributeMaxDynamicSharedMemorySize, GEMM_SMEM);

    // prep: fp16 splits
    split_x_kernel<<<(MTOK * (C_ / 4)) / 256, 256>>>(x);
    split_w_kernel<<<dim3(C3 / 32, C_ / 32), 256>>>(w_qkv, wq, C3);
    split_w_kernel<<<dim3(C_ / 32, C_ / 32), 256>>>(w_proj, wp, C_);

    // qkv = x @ w_qkv + b_qkv  (mma.sync fp16, 2-term split, shared B tile)
    gemm_mma_kernel<<<dim3(C3 / 128, MTOK / 128), 256, GEMM_SMEM>>>(xs, wq, b_qkv, qkv, C3);

    zero_attn_kernel<<<(B_ * H_ * D_ * D_ + 255) / 256, 256>>>();
    attn_qk_kernel<<<dim3(N_ / 256, B_ * H_), 256>>>();
    softmax_kernel<<<B_ * H_ * D_, 64>>>();
    v_attn_kernel<<<dim3(N_ / 64, B_ * H_), 256>>>();

    // out = mid @ w_proj + b_proj
    gemm_mma_kernel<<<dim3(C_ / 128, MTOK / 128), 256, GEMM_SMEM>>>(ms, wp, b_proj, out, C_);
}